// round 17
// baseline (speedup 1.0000x reference)
#include <cuda_runtime.h>
#include <cuda_fp16.h>
#include <cstdint>

#define MTOT 172032
#define DM   768
#define MT_TILES 1344

// resident A plane: h1, 128 rows x 776 halfs (768 + 4 pad) = 1552 B/row (conflict-free)
#define H1PITCH 1552
#define H1_BYTES (128 * H1PITCH)     // 198656

// residual x~ : two chunk planes, pitch 64 (no pad)
#define XPITCH 64
#define XPL (128 * XPITCH)           // 8192
#define SOFF_X24 H1_BYTES            // 198656
#define SOFF_X25 (SOFF_X24 + XPL)    // 206848

// B ring: pitch 64
#define BPITCH 64
#define BPL (128 * BPITCH)           // 8192
#define SOFF_B0 (SOFF_X25 + XPL)     // 215040
#define SOFF_B1 (SOFF_B0 + BPL)      // 223232
#define SMEM_FUSED (SOFF_B1 + BPL)   // 231424  (< 232448 limit)

// phase-1 staging (lives where XA/B ring will later live; used only before them)
#define HPITCH 112
#define HPL (128 * HPITCH)           // 14336
#define SOFF_A48 H1_BYTES            // 198656
#define SOFF_B48 (SOFF_A48 + HPL)    // 212992 (ends 227328 <= 231424)

// ---------------- global scratch (fp16) ----------------
__device__ __half g_x  [(size_t)MTOT * 64];   // [m][64] (k>=48 zero)
__device__ __half g_x48[(size_t)MTOT * 48];   // [m][48]
__device__ __half g_w2 [DM * DM];             // [n][k]
__device__ __half g_cw [DM * 64];             // [n][64] (k>=48 zero)
__device__ __half g_cw1[DM * 48];             // (cw^T @ w1)^T, [n][48]

// ---------------- helpers ----------------
__device__ __forceinline__ uint32_t smem_u32(const void* p) {
    uint32_t a;
    asm("{ .reg .u64 t; cvta.to.shared.u64 t, %1; cvt.u32.u64 %0, t; }" : "=r"(a) : "l"(p));
    return a;
}
__device__ __forceinline__ void cp16(uint32_t s, const void* g) {
    asm volatile("cp.async.cg.shared.global [%0], [%1], 16;" ::
                 "r"(s), "l"(__cvta_generic_to_global(g)));
}
#define CP_COMMIT() asm volatile("cp.async.commit_group;" ::: "memory")
template <int N>
__device__ __forceinline__ void cp_wait() {
    asm volatile("cp.async.wait_group %0;" :: "n"(N) : "memory");
}

__device__ __forceinline__ void ldmat4(uint32_t (&r)[4], uint32_t a) {
    asm volatile("ldmatrix.sync.aligned.m8n8.x4.shared.b16 {%0,%1,%2,%3}, [%4];"
                 : "=r"(r[0]), "=r"(r[1]), "=r"(r[2]), "=r"(r[3]) : "r"(a));
}
__device__ __forceinline__ void mma16816(float (&d)[4], const uint32_t* a, uint32_t b0, uint32_t b1) {
    asm volatile("mma.sync.aligned.m16n8k16.row.col.f32.f16.f16.f32 "
                 "{%0,%1,%2,%3},{%4,%5,%6,%7},{%8,%9},{%0,%1,%2,%3};"
                 : "+f"(d[0]), "+f"(d[1]), "+f"(d[2]), "+f"(d[3])
                 : "r"(a[0]), "r"(a[1]), "r"(a[2]), "r"(a[3]), "r"(b0), "r"(b1));
}

// ---- one BK=32 chunk; A at aBase (pitch AP), B at stgB (pitch BPITCH) ----
template <int AP>
__device__ __forceinline__ void compute_chunk2(uint32_t aBase, uint32_t stgB,
                                               int wm, int wn, int lane,
                                               float (&acc)[2][8][4]) {
    uint32_t r16a = (uint32_t)(lane & 15) * AP;
    uint32_t r16b = (uint32_t)(lane & 15) * BPITCH;
    uint32_t khalf = (uint32_t)(lane >> 4) * 16;
#pragma unroll
    for (int k16 = 0; k16 < 2; k16++) {
        uint32_t kc = khalf + (uint32_t)(k16 * 32);
        uint32_t af[2][4];
#pragma unroll
        for (int mf = 0; mf < 2; mf++)
            ldmat4(af[mf], aBase + (uint32_t)(wm + mf * 16) * AP + r16a + kc);
#pragma unroll
        for (int ng = 0; ng < 4; ng++) {
            uint32_t bf[4];
            ldmat4(bf, stgB + (uint32_t)(wn + ng * 16) * BPITCH + r16b + kc);
#pragma unroll
            for (int mf = 0; mf < 2; mf++)
#pragma unroll
                for (int sub = 0; sub < 2; sub++) {
                    int nf = ng * 2 + sub;
                    uint32_t b0 = sub ? bf[1] : bf[0];
                    uint32_t b1 = sub ? bf[3] : bf[2];
                    mma16816(acc[mf][nf], af[mf], b0, b1);
                }
        }
    }
}

// ---- B stage loader (one 128x32 chunk, pitch 64) ----
template <int BS>
__device__ __forceinline__ void load_B(uint32_t stg, const __half* __restrict__ B, int tid) {
#pragma unroll
    for (int it = 0; it < 2; it++) {
        int idx = tid + it * 256;                  // 0..511
        int row = idx >> 2, c = idx & 3;
        cp16(stg + (uint32_t)row * BPITCH + (uint32_t)c * 16, B + (size_t)row * BS + c * 8);
    }
}

// ---------------- merged prep ----------------
#define NX ((size_t)MTOT * 64)
#define NW (DM * DM)
#define NC (DM * 64)
__global__ void k_prep(const float* __restrict__ w2, const float* __restrict__ cw,
                       const float* __restrict__ x) {
    size_t gid = (size_t)blockIdx.x * 256 + threadIdx.x;
    if (gid < NX) {
        int m = (int)(gid >> 6), k = (int)(gid & 63);
        int seq = m >> 7, r = m & 127;
        __half v = __float2half(0.f);
        if (k < 48) {
            int t = k >> 4, i = k & 15;
            int pp = (r + t + 127) & 127;
            int j = pp * 8 + i;
            if (j > 1023) j = 1023;
            v = __float2half(x[(size_t)seq * 1024 + j]);
            g_x48[(size_t)m * 48 + k] = v;
        }
        g_x[gid] = v;
        return;
    }
    size_t g2 = gid - NX;
    if (g2 < NW) {
        int k = (int)(g2 / DM), n = (int)(g2 - (size_t)k * DM);
        g_w2[(size_t)n * DM + k] = __float2half(w2[g2]);
        return;
    }
    size_t g3 = g2 - NW;
    if (g3 < NC) {
        int n = (int)(g3 >> 6), k = (int)(g3 & 63);
        float v = 0.f;
        if (k < 48) { int i = k & 15, t = k >> 4; v = cw[n * 48 + i * 3 + t]; }
        g_cw[g3] = __float2half(v);
    }
}

// ---------------- cw1[n][k] = sum_d conv_w[d][map(k)] * w1[d][n] ----------------
__global__ void k_cw1(const float* __restrict__ cw, const float* __restrict__ w1) {
    __shared__ float col[768];
    int k = blockIdx.x;                // 0..47
    int i = k & 15, t = k >> 4;
    for (int d = threadIdx.x; d < 768; d += 128) col[d] = cw[d * 48 + i * 3 + t];
    __syncthreads();
    int n = blockIdx.y * 128 + threadIdx.x;
    float s = 0.f;
#pragma unroll 8
    for (int d = 0; d < 768; d++) s += col[d] * w1[(size_t)d * 768 + n];
    g_cw1[(size_t)n * 48 + k] = __float2half(s);
}

// ---------------- fused: phase1 h1->smem, phase2 out ----------------
#define NCH_MAIN 24
#define NCH_ALL  26
__global__ void __launch_bounds__(256, 1) k_fused(const float* __restrict__ b1,
                                                  const float* __restrict__ b2,
                                                  float* __restrict__ outF) {
    extern __shared__ __align__(128) char smem[];
    uint32_t sb = smem_u32(smem);
    int tid = threadIdx.x, wid = tid >> 5, lane = tid & 31;
    int wm = (wid & 3) * 32, wn = (wid >> 2) * 64;
    int m0 = blockIdx.x * 128;
    int rin = lane >> 2, colp = (lane & 3) * 2;

    // ================= phase 1: h1 tile (128 x 768) into smem plane =================
#pragma unroll
    for (int it = 0; it < 3; it++) {
        int idx = tid + it * 256;                 // 0..767
        int row = idx / 6, c = idx - row * 6;
        cp16(sb + SOFF_A48 + (uint32_t)row * HPITCH + (uint32_t)c * 16,
             g_x48 + (size_t)(m0 + row) * 48 + c * 8);
    }

#pragma unroll 1
    for (int n0p = 0; n0p < 6; n0p++) {
        int n0 = n0p * 128;
#pragma unroll
        for (int it = 0; it < 3; it++) {
            int idx = tid + it * 256;
            int row = idx / 6, c = idx - row * 6;
            cp16(sb + SOFF_B48 + (uint32_t)row * HPITCH + (uint32_t)c * 16,
                 g_cw1 + (size_t)(n0 + row) * 48 + c * 8);
        }
        CP_COMMIT();
        cp_wait<0>();
        __syncthreads();

        float acc[2][8][4];
#pragma unroll
        for (int a = 0; a < 2; a++)
#pragma unroll
            for (int b = 0; b < 8; b++)
#pragma unroll
                for (int c = 0; c < 4; c++) acc[a][b][c] = 0.f;

        {
            uint32_t r16 = (uint32_t)(lane & 15) * HPITCH;
            uint32_t khalf = (uint32_t)(lane >> 4) * 16;
#pragma unroll
            for (int k16 = 0; k16 < 3; k16++) {
                uint32_t kc = khalf + (uint32_t)(k16 * 32);
                uint32_t af[2][4];
#pragma unroll
                for (int mf = 0; mf < 2; mf++)
                    ldmat4(af[mf], sb + SOFF_A48 + (uint32_t)(wm + mf * 16) * HPITCH + r16 + kc);
#pragma unroll
                for (int ng = 0; ng < 4; ng++) {
                    uint32_t bf[4];
                    ldmat4(bf, sb + SOFF_B48 + (uint32_t)(wn + ng * 16) * HPITCH + r16 + kc);
#pragma unroll
                    for (int mf = 0; mf < 2; mf++)
#pragma unroll
                        for (int sub = 0; sub < 2; sub++) {
                            int nf = ng * 2 + sub;
                            uint32_t bb0 = sub ? bf[1] : bf[0];
                            uint32_t bb1 = sub ? bf[3] : bf[2];
                            mma16816(acc[mf][nf], af[mf], bb0, bb1);
                        }
                }
            }
        }

        // bias + relu -> fp16 into resident h1 plane
#pragma unroll
        for (int mf = 0; mf < 2; mf++)
#pragma unroll
            for (int nf = 0; nf < 8; nf++) {
                int cn = wn + nf * 8 + colp;
                float bb0 = b1[n0 + cn], bb1 = b1[n0 + cn + 1];
#pragma unroll
                for (int half = 0; half < 2; half++) {
                    int rr = wm + mf * 16 + rin + half * 8;
                    __half2 hp;
                    hp.x = __float2half(fmaxf(acc[mf][nf][half * 2] + bb0, 0.f));
                    hp.y = __float2half(fmaxf(acc[mf][nf][half * 2 + 1] + bb1, 0.f));
                    *(__half2*)(smem + (size_t)rr * H1PITCH + (n0 + cn) * 2) = hp;
                }
            }
        __syncthreads();
    }

    // load x~ as TWO pitch-64 chunk planes (region of stale A48 — all reads done)
#pragma unroll
    for (int it = 0; it < 4; it++) {
        int idx = tid + it * 256;                  // 0..1023
        int ch = idx >> 9;                         // chunk 0/1
        int i = idx & 511;
        int row = i >> 2, c = i & 3;
        cp16(sb + SOFF_X24 + (uint32_t)ch * XPL + (uint32_t)row * XPITCH + (uint32_t)c * 16,
             g_x + (size_t)(m0 + row) * 64 + ch * 32 + c * 8);
    }
    CP_COMMIT();
    cp_wait<0>();
    __syncthreads();

    // ================= phase 2: 6 output n-tiles =================
#pragma unroll 1
    for (int n0t = 0; n0t < 6; n0t++) {
        int n0 = n0t * 128;
        const __half* Bm = g_w2 + (size_t)n0 * DM;
        const __half* Br = g_cw + (size_t)n0 * 64;

        load_B<DM>(sb + SOFF_B0, Bm + 0 * 32, tid);
        CP_COMMIT();
        load_B<DM>(sb + SOFF_B1, Bm + 1 * 32, tid);
        CP_COMMIT();

        float acc[2][8][4];
#pragma unroll
        for (int a = 0; a < 2; a++)
#pragma unroll
            for (int b = 0; b < 8; b++)
#pragma unroll
                for (int c = 0; c < 4; c++) acc[a][b][c] = 0.f;

#pragma unroll 1
        for (int c = 0; c < NCH_ALL; c++) {
            cp_wait<1>();
            __syncthreads();
            uint32_t stgB = sb + SOFF_B0 + (uint32_t)(c & 1) * BPL;
            if (c < NCH_MAIN) {
                compute_chunk2<H1PITCH>(sb + (uint32_t)c * 64, stgB, wm, wn, lane, acc);
            } else {
                compute_chunk2<XPITCH>(sb + SOFF_X24 + (uint32_t)(c - NCH_MAIN) * XPL,
                                       stgB, wm, wn, lane, acc);
            }
            __syncthreads();
            int cn = c + 2;
            if (cn < NCH_MAIN) {
                load_B<DM>(stgB, Bm + cn * 32, tid);
            } else if (cn < NCH_ALL) {
                load_B<64>(stgB, Br + (cn - NCH_MAIN) * 32, tid);
            }
            CP_COMMIT();
        }

        // epilogue: direct float2 stores (4 lanes -> 32B contiguous)
#pragma unroll
        for (int mf = 0; mf < 2; mf++)
#pragma unroll
            for (int nf = 0; nf < 8; nf++) {
                int cn = wn + nf * 8 + colp;
                float bb0 = b2[n0 + cn], bb1 = b2[n0 + cn + 1];
#pragma unroll
                for (int half = 0; half < 2; half++) {
                    int gm = m0 + wm + mf * 16 + rin + half * 8;
                    float2 v;
                    v.x = acc[mf][nf][half * 2] + bb0;
                    v.y = acc[mf][nf][half * 2 + 1] + bb1;
                    *(float2*)(outF + (size_t)gm * DM + n0 + cn) = v;
                }
            }
        __syncthreads();   // B ring reuse safety across tiles
    }
}

// ---------------- launcher ----------------
extern "C" void kernel_launch(void* const* d_in, const int* in_sizes, int n_in,
                              void* d_out, int out_size) {
    (void)in_sizes; (void)n_in; (void)out_size;
    const float* x      = (const float*)d_in[0];
    const float* conv_w = (const float*)d_in[1];
    const float* w1     = (const float*)d_in[2];
    const float* b1     = (const float*)d_in[3];
    const float* w2     = (const float*)d_in[4];
    const float* b2     = (const float*)d_in[5];
    float* out = (float*)d_out;

    cudaFuncSetAttribute((const void*)k_fused,
                         cudaFuncAttributeMaxDynamicSharedMemorySize, SMEM_FUSED);

    size_t total = NX + (size_t)NW + NC;
    k_prep<<<(unsigned)((total + 255) / 256), 256>>>(w2, conv_w, x);
    {
        dim3 g(48, 6);
        k_cw1<<<g, 128>>>(conv_w, w1);
    }
    k_fused<<<MT_TILES, 256, SMEM_FUSED>>>(b1, b2, out);
}